// round 1
// baseline (speedup 1.0000x reference)
#include <cuda_runtime.h>
#include <cstdint>

// Shapes (fixed): B=8, A=8, T=128, F=64, H=128.  M = B*A*T = 8192 rows.
#define NBA   64      // B*A
#define TT    128
#define FF    64
#define HH    128
#define MROWS 8192

// Scratch for softmax gate weights w_t [M, F]  (2 MB) — __device__ global (no allocs allowed).
__device__ float g_wt[MROWS * FF];

// ---------------------------------------------------------------------------
// packed f32x2 helpers (ptxas won't auto-fuse; PTX-only path, 2x FFMA rate)
// ---------------------------------------------------------------------------
__device__ __forceinline__ unsigned long long pack2(float lo, float hi) {
    unsigned long long r;
    asm("mov.b64 %0, {%1, %2};" : "=l"(r) : "f"(lo), "f"(hi));
    return r;
}
__device__ __forceinline__ void fma2(unsigned long long& d, unsigned long long a, unsigned long long b) {
    asm("fma.rn.f32x2 %0, %1, %2, %0;" : "+l"(d) : "l"(a), "l"(b));
}

// ---------------------------------------------------------------------------
// Kernel A: gating FFN + softmax over T.  One CTA per (b,a). 256 threads.
// smem: xs[128][64] | ss[128][64] | w1s[64][128] | w2s[64][128] (w3s aliases
// nothing; separate g1s region) | g1s[128][128] | red[512]
// ---------------------------------------------------------------------------
#define GATE_SMEM_FLOATS (8192 + 8192 + 8192 + 8192 + 16384 + 512)
#define GATE_SMEM_BYTES  (GATE_SMEM_FLOATS * 4)

__global__ __launch_bounds__(256, 1)
void gating_kernel(const float* __restrict__ x, const float* __restrict__ s,
                   const float* __restrict__ w1, const float* __restrict__ b1,
                   const float* __restrict__ w2, const float* __restrict__ b2,
                   const float* __restrict__ w3, const float* __restrict__ b3)
{
    extern __shared__ float sm[];
    float* xs  = sm;             // 8192  [t][f]
    float* ss  = sm + 8192;      // 8192  [t][f]
    float* w1s = sm + 16384;     // 8192  [f][h]   (reused as w3s [h][f] in phase 2)
    float* w2s = sm + 24576;     // 8192  [f][h]   (reused as g_s [t][f] in phase 2)
    float* g1s = sm + 32768;     // 16384 [t][h]
    float* red = sm + 49152;     // 512

    const int tid = threadIdx.x;
    const int ba  = blockIdx.x;
    const float* xg = x + ba * (TT * FF);
    const float* sg = s + ba * (TT * FF);

    for (int i = tid; i < TT * FF; i += 256) {
        xs[i]  = xg[i];
        ss[i]  = sg[i];
        w1s[i] = w1[i];
        w2s[i] = w2[i];
    }
    __syncthreads();

    // ---- phase 1: g1[t][h] = elu( sum_f x*w1 + s*w2 + b1 + b2 ) ----
    {
        const int h    = tid & 127;
        const int half = tid >> 7;        // 0..1
        const float bb = b1[h] + b2[h];
        for (int c = 0; c < 4; c++) {
            const int t0 = half * 64 + c * 16;
            float acc[16];
#pragma unroll
            for (int tt = 0; tt < 16; tt++) acc[tt] = bb;
            for (int f = 0; f < FF; f += 4) {
                float w1v[4], w2v[4];
#pragma unroll
                for (int k = 0; k < 4; k++) {
                    w1v[k] = w1s[(f + k) * HH + h];
                    w2v[k] = w2s[(f + k) * HH + h];
                }
#pragma unroll
                for (int tt = 0; tt < 16; tt++) {
                    const float4 xv = *(const float4*)&xs[(t0 + tt) * FF + f];
                    const float4 sv = *(const float4*)&ss[(t0 + tt) * FF + f];
                    float a = acc[tt];
                    a = fmaf(xv.x, w1v[0], a); a = fmaf(xv.y, w1v[1], a);
                    a = fmaf(xv.z, w1v[2], a); a = fmaf(xv.w, w1v[3], a);
                    a = fmaf(sv.x, w2v[0], a); a = fmaf(sv.y, w2v[1], a);
                    a = fmaf(sv.z, w2v[2], a); a = fmaf(sv.w, w2v[3], a);
                    acc[tt] = a;
                }
            }
#pragma unroll
            for (int tt = 0; tt < 16; tt++) {
                float v = acc[tt];
                v = (v > 0.f) ? v : (__expf(v) - 1.f);   // ELU
                g1s[(t0 + tt) * HH + h] = v;
            }
        }
    }
    __syncthreads();

    // w1s/w2s no longer needed: load w3 [h][f] into w1s region
    for (int i = tid; i < HH * FF; i += 256) w1s[i] = w3[i];
    __syncthreads();
    float* w3s = w1s;
    float* gsm = w2s;   // g [t][f]

    // ---- phase 2: g[t][f] = sum_h g1[t][h] * w3[h][f] + b3[f] ----
    {
        const int f = tid & 63;
        const int q = tid >> 6;           // 0..3
        const int tbase = q * 32;
        float acc[32];
        const float b3v = b3[f];
#pragma unroll
        for (int i = 0; i < 32; i++) acc[i] = b3v;
        for (int hc = 0; hc < HH; hc += 8) {
            float wc[8];
#pragma unroll
            for (int k = 0; k < 8; k++) wc[k] = w3s[(hc + k) * FF + f];
#pragma unroll
            for (int i = 0; i < 32; i++) {
                const float4 ga = *(const float4*)&g1s[(tbase + i) * HH + hc];
                const float4 gb = *(const float4*)&g1s[(tbase + i) * HH + hc + 4];
                float a = acc[i];
                a = fmaf(ga.x, wc[0], a); a = fmaf(ga.y, wc[1], a);
                a = fmaf(ga.z, wc[2], a); a = fmaf(ga.w, wc[3], a);
                a = fmaf(gb.x, wc[4], a); a = fmaf(gb.y, wc[5], a);
                a = fmaf(gb.z, wc[6], a); a = fmaf(gb.w, wc[7], a);
                acc[i] = a;
            }
        }
#pragma unroll
        for (int i = 0; i < 32; i++) gsm[(tbase + i) * FF + f] = acc[i];
    }
    __syncthreads();

    // ---- softmax over t (per f), write w_t to global scratch ----
    {
        const int f = tid & 63;
        const int q = tid >> 6;
        const int tbase = q * 32;
        float m = -1e30f;
        for (int i = 0; i < 32; i++) m = fmaxf(m, gsm[(tbase + i) * FF + f]);
        red[q * 64 + f] = m;
        __syncthreads();
        const float gm = fmaxf(fmaxf(red[f], red[64 + f]),
                               fmaxf(red[128 + f], red[192 + f]));
        float ps = 0.f;
        for (int i = 0; i < 32; i++) {
            const float e = __expf(gsm[(tbase + i) * FF + f] - gm);
            gsm[(tbase + i) * FF + f] = e;
            ps += e;
        }
        red[256 + q * 64 + f] = ps;
        __syncthreads();
        const float inv = 1.f / (red[256 + f] + red[320 + f] + red[384 + f] + red[448 + f]);
        float* wtg = g_wt + ba * (TT * FF);
        for (int i = 0; i < 32; i++)
            wtg[(tbase + i) * FF + f] = gsm[(tbase + i) * FF + f] * inv;
    }
}

// ---------------------------------------------------------------------------
// Kernel B: out[M,128] = sum_f A_f[M,128] @ jw3[f]  (+ gated jb3 bias)
//   A_f[m,h] = w_t[m,f] * elu(x[m,f]*jw1[f,h] + jb1[f,h]),  generated on the fly.
// CTA tile: 64 rows x 128 cols, 256 threads, thread tile 4m x 8n (packed f32x2).
// smem: Bs[128][128] fp32 | As2[128][64] float2(v,v) | xs[64][64] | wts[64][64]
// ---------------------------------------------------------------------------
#define MAIN_SMEM_FLOATS (16384 + 16384 + 4096 + 4096)
#define MAIN_SMEM_BYTES  (MAIN_SMEM_FLOATS * 4)

__global__ __launch_bounds__(256, 1)
void main_kernel(const float* __restrict__ x,
                 const float* __restrict__ jw1, const float* __restrict__ jb1,
                 const float* __restrict__ jw3, const float* __restrict__ jb3,
                 float* __restrict__ out)
{
    extern __shared__ float sm[];
    float* Bs = sm;                                          // 16384: [hh][128]
    unsigned long long* As2 = (unsigned long long*)(sm + 16384); // 8192 ull: [hh][64] = (v,v)
    float* xs  = sm + 32768;                                 // 4096: [m][64]
    float* wts = sm + 36864;                                 // 4096: [m][64]

    const int tid = threadIdx.x;
    const int r0  = blockIdx.x * 64;

    for (int i = tid; i < 64 * FF; i += 256) {
        xs[i]  = x[r0 * FF + i];
        wts[i] = g_wt[r0 * FF + i];
    }

    const int tj = tid & 15;          // n group
    const int ti = tid >> 4;          // m group (0..15)
    const int m0 = ti * 4;
    const int n0j = tj * 4;           // in ull units (8 floats)

    unsigned long long acc[4][4];
#pragma unroll
    for (int i = 0; i < 4; i++)
#pragma unroll
        for (int j = 0; j < 4; j++) acc[i][j] = 0ULL;

    const int am = tid & 63;          // this thread's m for A staging
    const int hb = tid >> 6;          // 0..3
    const unsigned long long* Bsu = (const unsigned long long*)Bs;

    __syncthreads();   // xs/wts ready

    for (int f = 0; f < FF; f++) {
        // stage B = jw3[f] (128x128) into smem
        {
            const float4* src = (const float4*)(jw3 + f * (HH * HH));
            float4* dst = (float4*)Bs;
            for (int i = tid; i < (HH * HH) / 4; i += 256) dst[i] = src[i];
        }
        // stage A_f tile, pre-broadcast as (v,v) packed pairs
        {
            const float* jw1f = jw1 + f * HH;
            const float* jb1f = jb1 + f * HH;
            const float xv = xs[am * FF + f];
            const float wv = wts[am * FF + f];
#pragma unroll 4
            for (int it = 0; it < 32; it++) {
                const int hh = hb + it * 4;
                float v = fmaf(xv, jw1f[hh], jb1f[hh]);
                v = (v > 0.f) ? v : (__expf(v) - 1.f);   // ELU
                const float av = wv * v;
                As2[hh * 64 + am] = pack2(av, av);
            }
        }
        __syncthreads();

        // 64x128x128 GEMM from smem, packed f32x2
#pragma unroll 4
        for (int hh = 0; hh < HH; hh++) {
            const ulonglong2 a01 = *(const ulonglong2*)&As2[hh * 64 + m0];
            const ulonglong2 a23 = *(const ulonglong2*)&As2[hh * 64 + m0 + 2];
            const ulonglong2 b01 = *(const ulonglong2*)&Bsu[hh * 64 + n0j];
            const ulonglong2 b23 = *(const ulonglong2*)&Bsu[hh * 64 + n0j + 2];
            fma2(acc[0][0], a01.x, b01.x); fma2(acc[0][1], a01.x, b01.y);
            fma2(acc[0][2], a01.x, b23.x); fma2(acc[0][3], a01.x, b23.y);
            fma2(acc[1][0], a01.y, b01.x); fma2(acc[1][1], a01.y, b01.y);
            fma2(acc[1][2], a01.y, b23.x); fma2(acc[1][3], a01.y, b23.y);
            fma2(acc[2][0], a23.x, b01.x); fma2(acc[2][1], a23.x, b01.y);
            fma2(acc[2][2], a23.x, b23.x); fma2(acc[2][3], a23.x, b23.y);
            fma2(acc[3][0], a23.y, b01.x); fma2(acc[3][1], a23.y, b01.y);
            fma2(acc[3][2], a23.y, b23.x); fma2(acc[3][3], a23.y, b23.y);
        }

        // gated jb3 bias:  acc[i][:] += w_t[m0+i, f] * jb3[f, n]
        {
            const unsigned long long* jbu = (const unsigned long long*)(jb3 + f * HH);
            const ulonglong2 jb01 = *(const ulonglong2*)&jbu[n0j];
            const ulonglong2 jb23 = *(const ulonglong2*)&jbu[n0j + 2];
#pragma unroll
            for (int i = 0; i < 4; i++) {
                const float wvi = wts[(m0 + i) * FF + f];
                const unsigned long long w2 = pack2(wvi, wvi);
                fma2(acc[i][0], w2, jb01.x); fma2(acc[i][1], w2, jb01.y);
                fma2(acc[i][2], w2, jb23.x); fma2(acc[i][3], w2, jb23.y);
            }
        }
        __syncthreads();   // protect next iteration's smem overwrites
    }

    // epilogue: packed accumulators are bit-identical to 2 floats each
#pragma unroll
    for (int i = 0; i < 4; i++) {
        const int row = r0 + m0 + i;
        *(ulonglong2*)&out[row * HH + tj * 8]     = make_ulonglong2(acc[i][0], acc[i][1]);
        *(ulonglong2*)&out[row * HH + tj * 8 + 4] = make_ulonglong2(acc[i][2], acc[i][3]);
    }
}

// ---------------------------------------------------------------------------
extern "C" void kernel_launch(void* const* d_in, const int* in_sizes, int n_in,
                              void* d_out, int out_size)
{
    (void)in_sizes; (void)n_in; (void)out_size;
    const float* x   = (const float*)d_in[0];
    const float* s   = (const float*)d_in[1];
    const float* w1  = (const float*)d_in[2];
    const float* b1  = (const float*)d_in[3];
    const float* w2  = (const float*)d_in[4];
    const float* b2  = (const float*)d_in[5];
    const float* w3  = (const float*)d_in[6];
    const float* b3  = (const float*)d_in[7];
    const float* jw1 = (const float*)d_in[8];
    const float* jb1 = (const float*)d_in[9];
    const float* jw3 = (const float*)d_in[10];
    const float* jb3 = (const float*)d_in[11];
    float* out = (float*)d_out;

    cudaFuncSetAttribute(gating_kernel, cudaFuncAttributeMaxDynamicSharedMemorySize, GATE_SMEM_BYTES);
    cudaFuncSetAttribute(main_kernel,   cudaFuncAttributeMaxDynamicSharedMemorySize, MAIN_SMEM_BYTES);

    gating_kernel<<<NBA, 256, GATE_SMEM_BYTES>>>(x, s, w1, b1, w2, b2, w3, b3);
    main_kernel<<<MROWS / 64, 256, MAIN_SMEM_BYTES>>>(x, jw1, jb1, jw3, jb3, out);
}

// round 3
// speedup vs baseline: 2.0755x; 2.0755x over previous
#include <cuda_runtime.h>
#include <cstdint>

// Shapes (fixed): B=8, A=8, T=128, F=64, H=128.  M = B*A*T = 8192 rows.
#define NBA   64
#define TT    128
#define FF    64
#define HH    128
#define MROWS 8192

__device__ float g_wt[MROWS * FF];            // softmax gate weights [M][F]  (2 MB)
__device__ float g_part[2][MROWS * HH];       // split-K partials (8 MB)

// ---------------------------------------------------------------------------
// packed f32x2 helpers
// ---------------------------------------------------------------------------
__device__ __forceinline__ unsigned long long pack2(float lo, float hi) {
    unsigned long long r;
    asm("mov.b64 %0, {%1, %2};" : "=l"(r) : "f"(lo), "f"(hi));
    return r;
}
__device__ __forceinline__ void fma2(unsigned long long& d, unsigned long long a, unsigned long long b) {
    asm("fma.rn.f32x2 %0, %1, %2, %0;" : "+l"(d) : "l"(a), "l"(b));
}
__device__ __forceinline__ unsigned smem_u32(const void* p) {
    unsigned a;
    asm("{ .reg .u64 t; cvta.to.shared.u64 t, %1; cvt.u32.u64 %0, t; }" : "=r"(a) : "l"(p));
    return a;
}
__device__ __forceinline__ void cpasync16(unsigned dst, const float* src) {
    asm volatile("cp.async.cg.shared.global [%0], [%1], 16;" :: "r"(dst), "l"(src));
}
#define CP_COMMIT()  asm volatile("cp.async.commit_group;")
#define CP_WAIT(n)   asm volatile("cp.async.wait_group %0;" :: "n"(n))

// ---------------------------------------------------------------------------
// Kernel A: gating FFN + softmax over T.  One CTA per (b,a). 256 threads.
// ---------------------------------------------------------------------------
#define GATE_SMEM_FLOATS (8192 + 8192 + 8192 + 8192 + 16384 + 512)
#define GATE_SMEM_BYTES  (GATE_SMEM_FLOATS * 4)

__global__ __launch_bounds__(256, 1)
void gating_kernel(const float* __restrict__ x, const float* __restrict__ s,
                   const float* __restrict__ w1, const float* __restrict__ b1,
                   const float* __restrict__ w2, const float* __restrict__ b2,
                   const float* __restrict__ w3, const float* __restrict__ b3)
{
    extern __shared__ float sm[];
    float* xs  = sm;
    float* ss  = sm + 8192;
    float* w1s = sm + 16384;
    float* w2s = sm + 24576;
    float* g1s = sm + 32768;
    float* red = sm + 49152;

    const int tid = threadIdx.x;
    const int ba  = blockIdx.x;
    const float* xg = x + ba * (TT * FF);
    const float* sg = s + ba * (TT * FF);

    for (int i = tid; i < TT * FF; i += 256) {
        xs[i]  = xg[i];
        ss[i]  = sg[i];
        w1s[i] = w1[i];
        w2s[i] = w2[i];
    }
    __syncthreads();

    {
        const int h    = tid & 127;
        const int half = tid >> 7;
        const float bb = b1[h] + b2[h];
        for (int c = 0; c < 4; c++) {
            const int t0 = half * 64 + c * 16;
            float acc[16];
#pragma unroll
            for (int tt = 0; tt < 16; tt++) acc[tt] = bb;
            for (int f = 0; f < FF; f += 4) {
                float w1v[4], w2v[4];
#pragma unroll
                for (int k = 0; k < 4; k++) {
                    w1v[k] = w1s[(f + k) * HH + h];
                    w2v[k] = w2s[(f + k) * HH + h];
                }
#pragma unroll
                for (int tt = 0; tt < 16; tt++) {
                    const float4 xv = *(const float4*)&xs[(t0 + tt) * FF + f];
                    const float4 sv = *(const float4*)&ss[(t0 + tt) * FF + f];
                    float a = acc[tt];
                    a = fmaf(xv.x, w1v[0], a); a = fmaf(xv.y, w1v[1], a);
                    a = fmaf(xv.z, w1v[2], a); a = fmaf(xv.w, w1v[3], a);
                    a = fmaf(sv.x, w2v[0], a); a = fmaf(sv.y, w2v[1], a);
                    a = fmaf(sv.z, w2v[2], a); a = fmaf(sv.w, w2v[3], a);
                    acc[tt] = a;
                }
            }
#pragma unroll
            for (int tt = 0; tt < 16; tt++) {
                float v = acc[tt];
                v = (v > 0.f) ? v : (__expf(v) - 1.f);
                g1s[(t0 + tt) * HH + h] = v;
            }
        }
    }
    __syncthreads();

    for (int i = tid; i < HH * FF; i += 256) w1s[i] = w3[i];
    __syncthreads();
    float* w3s = w1s;
    float* gsm = w2s;

    {
        const int f = tid & 63;
        const int q = tid >> 6;
        const int tbase = q * 32;
        float acc[32];
        const float b3v = b3[f];
#pragma unroll
        for (int i = 0; i < 32; i++) acc[i] = b3v;
        for (int hc = 0; hc < HH; hc += 8) {
            float wc[8];
#pragma unroll
            for (int k = 0; k < 8; k++) wc[k] = w3s[(hc + k) * FF + f];
#pragma unroll
            for (int i = 0; i < 32; i++) {
                const float4 ga = *(const float4*)&g1s[(tbase + i) * HH + hc];
                const float4 gb = *(const float4*)&g1s[(tbase + i) * HH + hc + 4];
                float a = acc[i];
                a = fmaf(ga.x, wc[0], a); a = fmaf(ga.y, wc[1], a);
                a = fmaf(ga.z, wc[2], a); a = fmaf(ga.w, wc[3], a);
                a = fmaf(gb.x, wc[4], a); a = fmaf(gb.y, wc[5], a);
                a = fmaf(gb.z, wc[6], a); a = fmaf(gb.w, wc[7], a);
                acc[i] = a;
            }
        }
#pragma unroll
        for (int i = 0; i < 32; i++) gsm[(tbase + i) * FF + f] = acc[i];
    }
    __syncthreads();

    {
        const int f = tid & 63;
        const int q = tid >> 6;
        const int tbase = q * 32;
        float m = -1e30f;
        for (int i = 0; i < 32; i++) m = fmaxf(m, gsm[(tbase + i) * FF + f]);
        red[q * 64 + f] = m;
        __syncthreads();
        const float gm = fmaxf(fmaxf(red[f], red[64 + f]),
                               fmaxf(red[128 + f], red[192 + f]));
        float ps = 0.f;
        for (int i = 0; i < 32; i++) {
            const float e = __expf(gsm[(tbase + i) * FF + f] - gm);
            gsm[(tbase + i) * FF + f] = e;
            ps += e;
        }
        red[256 + q * 64 + f] = ps;
        __syncthreads();
        const float inv = 1.f / (red[256 + f] + red[320 + f] + red[384 + f] + red[448 + f]);
        float* wtg = g_wt + ba * (TT * FF);
        for (int i = 0; i < 32; i++)
            wtg[(tbase + i) * FF + f] = gsm[(tbase + i) * FF + f] * inv;
    }
}

// ---------------------------------------------------------------------------
// Kernel B: split-K(f) fused GEMM.
//   grid = 64 row-tiles x 2 f-halves.  512 threads.  CTA tile 128m x 128n x 32f.
//   per-thread 8m x 4n, packed f32x2 accumulators.
//   A_f generated on the fly (elu), B = jw3[f] double-buffered via cp.async.
// smem floats: Bs[2][128*128] | As[128*128] | xs[32][128] | wts[32][128]
// ---------------------------------------------------------------------------
#define MAIN_SMEM_FLOATS (32768 + 16384 + 4096 + 4096)
#define MAIN_SMEM_BYTES  (MAIN_SMEM_FLOATS * 4)   // 229376 B (<= 227KB opt-in)

__global__ __launch_bounds__(512, 1)
void main_kernel(const float* __restrict__ x,
                 const float* __restrict__ jw1, const float* __restrict__ jb1,
                 const float* __restrict__ jw3, const float* __restrict__ jb3)
{
    extern __shared__ float sm[];
    float* Bs  = sm;            // 2 x 16384: [buf][hh][128]
    float* As  = sm + 32768;    // 16384: [hh][128]
    float* xs  = sm + 49152;    // 4096:  [fi][128]
    float* wts = sm + 53248;    // 4096:  [fi][128]

    const int tid   = threadIdx.x;
    const int half  = blockIdx.x & 1;          // f-split
    const int tile  = blockIdx.x >> 1;         // row tile
    const int r0    = tile * 128;
    const int fbase = half * 32;

    const int ng = tid & 31;                   // n group: n0 = ng*4
    const int mg = tid >> 5;                   // m group: m0 = mg*8 (warp-uniform)
    const int m0 = mg * 8;
    const int n0 = ng * 4;

    const int am = tid & 127;                  // A-staging row
    const int hb = tid >> 7;                   // A-staging hh block (0..3)

    const unsigned bs_u = smem_u32(Bs);

    // stage x / w_t for this CTA's 128 rows x 32 f
    for (int i = tid; i < 32 * 128; i += 512) {
        const int fi = i >> 7, m = i & 127;
        xs[i]  = x[(r0 + m) * FF + fbase + fi];
        wts[i] = g_wt[(r0 + m) * FF + fbase + fi];
    }

    // prologue: cp.async B(f=0) into buf 0
    {
        const float* src = jw3 + (fbase + 0) * (HH * HH);
#pragma unroll
        for (int k = 0; k < 8; k++) {
            const int idx = tid + k * 512;     // float4 index
            cpasync16(bs_u + idx * 16, src + idx * 4);
        }
        CP_COMMIT();
    }

    unsigned long long acc[8][2];
#pragma unroll
    for (int i = 0; i < 8; i++) { acc[i][0] = 0ULL; acc[i][1] = 0ULL; }

    __syncthreads();   // xs/wts ready

    for (int fi = 0; fi < 32; fi++) {
        const int f = fbase + fi;

        // ---- generate A_f tile (elu) into As ----
        {
            const float xv = xs[fi * 128 + am];
            const float wv = wts[fi * 128 + am];
            const float4* jw1f = (const float4*)(jw1 + f * HH + hb * 32);
            const float4* jb1f = (const float4*)(jb1 + f * HH + hb * 32);
#pragma unroll
            for (int it = 0; it < 8; it++) {
                const float4 w = jw1f[it];
                const float4 b = jb1f[it];
                float v0 = fmaf(xv, w.x, b.x);
                float v1 = fmaf(xv, w.y, b.y);
                float v2 = fmaf(xv, w.z, b.z);
                float v3 = fmaf(xv, w.w, b.w);
                v0 = (v0 > 0.f) ? v0 : (__expf(v0) - 1.f);
                v1 = (v1 > 0.f) ? v1 : (__expf(v1) - 1.f);
                v2 = (v2 > 0.f) ? v2 : (__expf(v2) - 1.f);
                v3 = (v3 > 0.f) ? v3 : (__expf(v3) - 1.f);
                const int hh = hb * 32 + it * 4;
                As[(hh + 0) * 128 + am] = wv * v0;
                As[(hh + 1) * 128 + am] = wv * v1;
                As[(hh + 2) * 128 + am] = wv * v2;
                As[(hh + 3) * 128 + am] = wv * v3;
            }
        }

        // ---- prefetch B(f+1) into other buffer ----
        if (fi + 1 < 32) {
            const float* src = jw3 + (f + 1) * (HH * HH);
            const unsigned dst = bs_u + ((fi + 1) & 1) * 65536;
#pragma unroll
            for (int k = 0; k < 8; k++) {
                const int idx = tid + k * 512;
                cpasync16(dst + idx * 16, src + idx * 4);
            }
            CP_COMMIT();
            CP_WAIT(1);           // B(f) complete, B(f+1) in flight
        } else {
            CP_WAIT(0);
        }
        __syncthreads();          // As + Bs[buf] visible to all

        // ---- 128x128x128 GEMM slice from smem ----
        {
            const float* Asp = As;
            const float* Bsp = Bs + (fi & 1) * 16384;
#pragma unroll 2
            for (int hh = 0; hh < HH; hh++) {
                const float4 a0 = *(const float4*)&Asp[hh * 128 + m0];      // broadcast
                const float4 a1 = *(const float4*)&Asp[hh * 128 + m0 + 4];  // broadcast
                const ulonglong2 b = *(const ulonglong2*)&Bsp[hh * 128 + n0];
                unsigned long long p0 = pack2(a0.x, a0.x);
                unsigned long long p1 = pack2(a0.y, a0.y);
                unsigned long long p2 = pack2(a0.z, a0.z);
                unsigned long long p3 = pack2(a0.w, a0.w);
                unsigned long long p4 = pack2(a1.x, a1.x);
                unsigned long long p5 = pack2(a1.y, a1.y);
                unsigned long long p6 = pack2(a1.z, a1.z);
                unsigned long long p7 = pack2(a1.w, a1.w);
                fma2(acc[0][0], p0, b.x); fma2(acc[0][1], p0, b.y);
                fma2(acc[1][0], p1, b.x); fma2(acc[1][1], p1, b.y);
                fma2(acc[2][0], p2, b.x); fma2(acc[2][1], p2, b.y);
                fma2(acc[3][0], p3, b.x); fma2(acc[3][1], p3, b.y);
                fma2(acc[4][0], p4, b.x); fma2(acc[4][1], p4, b.y);
                fma2(acc[5][0], p5, b.x); fma2(acc[5][1], p5, b.y);
                fma2(acc[6][0], p6, b.x); fma2(acc[6][1], p6, b.y);
                fma2(acc[7][0], p7, b.x); fma2(acc[7][1], p7, b.y);
            }
        }

        // ---- gated jb3 bias ----
        {
            const ulonglong2 jb = *(const ulonglong2*)&jb3[f * HH + n0];
#pragma unroll
            for (int i = 0; i < 8; i++) {
                const float wvi = wts[fi * 128 + m0 + i];   // broadcast
                const unsigned long long w2 = pack2(wvi, wvi);
                fma2(acc[i][0], w2, jb.x); fma2(acc[i][1], w2, jb.y);
            }
        }
        __syncthreads();          // protect As / Bs rewrite next iter
    }

    // ---- write split-K partial ----
    float* pout = g_part[half];
#pragma unroll
    for (int i = 0; i < 8; i++) {
        const int row = r0 + m0 + i;
        *(ulonglong2*)&pout[row * HH + n0] = make_ulonglong2(acc[i][0], acc[i][1]);
    }
}

// ---------------------------------------------------------------------------
// Combine kernel: out = part0 + part1   (writes every element of d_out)
// ---------------------------------------------------------------------------
__global__ __launch_bounds__(256, 1)
void combine_kernel(float* __restrict__ out)
{
    const int i = blockIdx.x * 256 + threadIdx.x;   // float4 index
    const float4 a = ((const float4*)g_part[0])[i];
    const float4 b = ((const float4*)g_part[1])[i];
    float4 r;
    r.x = a.x + b.x; r.y = a.y + b.y; r.z = a.z + b.z; r.w = a.w + b.w;
    ((float4*)out)[i] = r;
}

// ---------------------------------------------------------------------------
extern "C" void kernel_launch(void* const* d_in, const int* in_sizes, int n_in,
                              void* d_out, int out_size)
{
    (void)in_sizes; (void)n_in; (void)out_size;
    const float* x   = (const float*)d_in[0];
    const float* s   = (const float*)d_in[1];
    const float* w1  = (const float*)d_in[2];
    const float* b1  = (const float*)d_in[3];
    const float* w2  = (const float*)d_in[4];
    const float* b2  = (const float*)d_in[5];
    const float* w3  = (const float*)d_in[6];
    const float* b3  = (const float*)d_in[7];
    const float* jw1 = (const float*)d_in[8];
    const float* jb1 = (const float*)d_in[9];
    const float* jw3 = (const float*)d_in[10];
    const float* jb3 = (const float*)d_in[11];
    float* out = (float*)d_out;

    (void)cudaFuncSetAttribute(gating_kernel, cudaFuncAttributeMaxDynamicSharedMemorySize, GATE_SMEM_BYTES);
    (void)cudaFuncSetAttribute(main_kernel,   cudaFuncAttributeMaxDynamicSharedMemorySize, MAIN_SMEM_BYTES);

    gating_kernel<<<NBA, 256, GATE_SMEM_BYTES>>>(x, s, w1, b1, w2, b2, w3, b3);
    main_kernel<<<128, 512, MAIN_SMEM_BYTES>>>(x, jw1, jb1, jw3, jb3);
    combine_kernel<<<(MROWS * HH) / (4 * 256), 256>>>(out);
}

// round 6
// speedup vs baseline: 4.3672x; 2.1041x over previous
#include <cuda_runtime.h>
#include <cstdint>

// Shapes (fixed): B=8, A=8, T=128, F=64, H=128.  M = B*A*T = 8192 rows.
#define NBA   64
#define TT    128
#define FF    64
#define HH    128
#define MROWS 8192

__device__ float    g_wt  [MROWS * FF];     // softmax gate weights [M][F]   (2 MB)
__device__ float    g_ghat[MROWS * FF];     // pre-softmax logits            (2 MB)
__device__ float    g_part[2][MROWS * HH];  // split-K partials              (8 MB)
__device__ unsigned g_bf  [FF][16384];      // jw3^T fragment-packed tf32    (4 MB)
__device__ unsigned g_b2f [2][4096];        // jb3^T fragment-packed tf32    (32 KB)

// ---------------------------------------------------------------------------
// helpers
// ---------------------------------------------------------------------------
__device__ __forceinline__ unsigned smem_u32(const void* p) {
    unsigned a;
    asm("{ .reg .u64 t; cvta.to.shared.u64 t, %1; cvt.u32.u64 %0, t; }" : "=r"(a) : "l"(p));
    return a;
}
__device__ __forceinline__ void cpasync16(unsigned dst, const void* src) {
    asm volatile("cp.async.cg.shared.global [%0], [%1], 16;" :: "r"(dst), "l"(src));
}
#define CP_COMMIT()  asm volatile("cp.async.commit_group;")
#define CP_WAIT(n)   asm volatile("cp.async.wait_group %0;" :: "n"(n))

__device__ __forceinline__ unsigned tf32_rna(float x) {
    unsigned u;
    asm("cvt.rna.tf32.f32 %0, %1;" : "=r"(u) : "f"(x));
    return u;
}
__device__ __forceinline__ float eluf(float v) {
    return v > 0.f ? v : (__expf(v) - 1.f);
}

// m16n8k8 tf32 MMA (legacy tensor path; plain sm_100 target OK)
__device__ __forceinline__ void mma8(float* c, const uint4& a, const uint2& b) {
    asm volatile(
        "mma.sync.aligned.m16n8k8.row.col.f32.tf32.tf32.f32 "
        "{%0,%1,%2,%3}, {%4,%5,%6,%7}, {%8,%9}, {%0,%1,%2,%3};"
        : "+f"(c[0]), "+f"(c[1]), "+f"(c[2]), "+f"(c[3])
        : "r"(a.x), "r"(a.y), "r"(a.z), "r"(a.w), "r"(b.x), "r"(b.y));
}

// fragment packing index for B: element (k, n) within a 64k(or 32k) x 128n tile
//   ks = k>>3, c = k&3, comp = (k>>2)&1 ; nt = n>>3, g = n&7, lane = g*4+c
//   u32 index = (((ks*16 + nt)*32 + lane) << 1) + comp
__device__ __forceinline__ int bpack_idx(int k, int n) {
    return ((((k >> 3) * 16 + (n >> 3)) * 32 + (n & 7) * 4 + (k & 3)) << 1) + ((k >> 2) & 1);
}

// ---------------------------------------------------------------------------
// Prep kernel: fragment-pack jw3^T (per f, 2 chunks of 64h) and jb3^T (per half)
// grid 66 x 256
// ---------------------------------------------------------------------------
__global__ __launch_bounds__(256, 1)
void prep_kernel(const float* __restrict__ jw3, const float* __restrict__ jb3)
{
    const int blk = blockIdx.x, tid = threadIdx.x;
    if (blk < FF) {
        const int f = blk;
        const float* src = jw3 + f * (HH * HH);
        unsigned* dst = g_bf[f];
        for (int i = tid; i < HH * HH; i += 256) {
            const int h = i >> 7, n = i & 127;           // coalesced read over n
            const int chunk = h >> 6, kc = h & 63;
            dst[chunk * 8192 + bpack_idx(kc, n)] = tf32_rna(src[h * HH + n]);
        }
    } else {
        const int half = blk - FF;
        unsigned* dst = g_b2f[half];
        for (int i = tid; i < 32 * HH; i += 256) {
            const int k = i >> 7, n = i & 127;
            dst[bpack_idx(k, n)] = tf32_rna(jb3[(half * 32 + k) * HH + n]);
        }
    }
}

// ---------------------------------------------------------------------------
// Gating logits kernel: ghat[M,F].  grid 128 x 256, 64 rows per CTA.
// ---------------------------------------------------------------------------
#define LOG_SMEM_FLOATS (4096 + 4096 + 8192 + 8192 + 8192)
#define LOG_SMEM_BYTES  (LOG_SMEM_FLOATS * 4)

__global__ __launch_bounds__(256, 1)
void logits_kernel(const float* __restrict__ x, const float* __restrict__ s,
                   const float* __restrict__ w1, const float* __restrict__ b1,
                   const float* __restrict__ w2, const float* __restrict__ b2,
                   const float* __restrict__ w3, const float* __restrict__ b3)
{
    extern __shared__ float sm[];
    float* xs  = sm;            // [m(64)][f(64)]
    float* ss  = sm + 4096;
    float* w1s = sm + 8192;     // [f][h]
    float* w2s = sm + 16384;
    float* g1s = sm + 24576;    // [m(64)][h(128)]

    const int tid = threadIdx.x;
    const int r0  = blockIdx.x * 64;

    for (int i = tid; i < 64 * FF; i += 256) {
        xs[i] = x[r0 * FF + i];
        ss[i] = s[r0 * FF + i];
    }
    for (int i = tid; i < FF * HH; i += 256) {
        w1s[i] = w1[i];
        w2s[i] = w2[i];
    }
    __syncthreads();

    {
        const int h    = tid & 127;
        const int half = tid >> 7;
        const float bb = b1[h] + b2[h];
        for (int c = 0; c < 2; c++) {
            const int m0 = half * 32 + c * 16;
            float acc[16];
#pragma unroll
            for (int t = 0; t < 16; t++) acc[t] = bb;
            for (int f = 0; f < FF; f += 4) {
                float w1v[4], w2v[4];
#pragma unroll
                for (int k = 0; k < 4; k++) {
                    w1v[k] = w1s[(f + k) * HH + h];
                    w2v[k] = w2s[(f + k) * HH + h];
                }
#pragma unroll
                for (int t = 0; t < 16; t++) {
                    const float4 xv = *(const float4*)&xs[(m0 + t) * FF + f];
                    const float4 sv = *(const float4*)&ss[(m0 + t) * FF + f];
                    float a = acc[t];
                    a = fmaf(xv.x, w1v[0], a); a = fmaf(xv.y, w1v[1], a);
                    a = fmaf(xv.z, w1v[2], a); a = fmaf(xv.w, w1v[3], a);
                    a = fmaf(sv.x, w2v[0], a); a = fmaf(sv.y, w2v[1], a);
                    a = fmaf(sv.z, w2v[2], a); a = fmaf(sv.w, w2v[3], a);
                    acc[t] = a;
                }
            }
#pragma unroll
            for (int t = 0; t < 16; t++) g1s[(m0 + t) * HH + h] = eluf(acc[t]);
        }
    }
    __syncthreads();

    for (int i = tid; i < HH * FF; i += 256) w1s[i] = w3[i];   // w3s [h][f]
    __syncthreads();
    float* w3s = w1s;

    {
        const int f = tid & 63;
        const int q = tid >> 6;             // 0..3 -> rows q*16..+16
        const int m0 = q * 16;
        float acc[16];
        const float b3v = b3[f];
#pragma unroll
        for (int i = 0; i < 16; i++) acc[i] = b3v;
        for (int hc = 0; hc < HH; hc += 8) {
            float wc[8];
#pragma unroll
            for (int k = 0; k < 8; k++) wc[k] = w3s[(hc + k) * FF + f];
#pragma unroll
            for (int i = 0; i < 16; i++) {
                const float4 ga = *(const float4*)&g1s[(m0 + i) * HH + hc];
                const float4 gb = *(const float4*)&g1s[(m0 + i) * HH + hc + 4];
                float a = acc[i];
                a = fmaf(ga.x, wc[0], a); a = fmaf(ga.y, wc[1], a);
                a = fmaf(ga.z, wc[2], a); a = fmaf(ga.w, wc[3], a);
                a = fmaf(gb.x, wc[4], a); a = fmaf(gb.y, wc[5], a);
                a = fmaf(gb.z, wc[6], a); a = fmaf(gb.w, wc[7], a);
                acc[i] = a;
            }
        }
#pragma unroll
        for (int i = 0; i < 16; i++) g_ghat[(r0 + m0 + i) * FF + f] = acc[i];
    }
}

// ---------------------------------------------------------------------------
// Softmax kernel: w_t = softmax_T(ghat).  grid 64 (ba) x 512.
// ---------------------------------------------------------------------------
#define SMX_SMEM_BYTES ((8192 + 1024) * 4)

__global__ __launch_bounds__(512, 1)
void softmax_kernel()
{
    extern __shared__ float sm[];
    float* gs     = sm;           // [t(128)][f(64)]
    float* redmax = sm + 8192;
    float* redsum = sm + 8704;

    const int tid = threadIdx.x;
    const int ba  = blockIdx.x;
    for (int i = tid; i < TT * FF; i += 512) gs[i] = g_ghat[ba * (TT * FF) + i];
    __syncthreads();

    const int f  = tid & 63;
    const int q  = tid >> 6;       // 0..7
    const int t0 = q * 16;

    float mx = -1e30f;
    for (int i = 0; i < 16; i++) mx = fmaxf(mx, gs[(t0 + i) * FF + f]);
    redmax[q * 64 + f] = mx;
    __syncthreads();
    float gm = redmax[f];
    for (int k = 1; k < 8; k++) gm = fmaxf(gm, redmax[k * 64 + f]);

    float ps = 0.f;
    for (int i = 0; i < 16; i++) {
        const float e = __expf(gs[(t0 + i) * FF + f] - gm);
        gs[(t0 + i) * FF + f] = e;
        ps += e;
    }
    redsum[q * 64 + f] = ps;
    __syncthreads();
    float tot = redsum[f];
    for (int k = 1; k < 8; k++) tot += redsum[k * 64 + f];
    const float inv = 1.f / tot;

    for (int i = 0; i < 16; i++)
        g_wt[(ba * TT + t0 + i) * FF + f] = gs[(t0 + i) * FF + f] * inv;
}

// ---------------------------------------------------------------------------
// Main kernel: mma.sync tf32 fused GEMM.
//   grid = 64 row-tiles x 2 f-halves (128 CTAs), 512 threads (16 warps: 4m x 4n).
//   Per CTA: C[128m x 128n] in registers, K = 32f x 128h as 64 chunks of 64h,
//   + 4 bias K-steps (w_t @ jb3^T) done first.
//   A generated on the fly into fragment-packed smem (double-buffered);
//   B cp.async'd from pre-packed images (3-deep ring, 2 ahead).
// smem floats: A0 0 | A1 8192 | Bring 16384(3x8192) | A2 40960 | B2 45056 |
//              XS 49152 | WTS 53248   (total 57344 floats = 229376 B)
// ---------------------------------------------------------------------------
#define A0OFF   0
#define A1OFF   8192
#define BROFF   16384
#define A2OFF   40960
#define B2OFF   45056
#define XSOFF   49152
#define WTSOFF  53248
#define MAIN_SMEM_BYTES (57344 * 4)

__device__ __forceinline__ void gen_chunk(float* sm, int abuf_f,
                                          const float* xs, const float* wts,
                                          const float* jw1f, const float* jb1f,
                                          int fi, int hbase, int tid)
{
    uint4* dst = (uint4*)(sm + abuf_f);
#pragma unroll
    for (int j = 0; j < 4; j++) {
        const int s    = tid + j * 512;       // slot id 0..2047
        const int lane = s & 31;
        const int mt   = (s >> 5) & 7;
        const int ks   = s >> 8;
        const int g    = lane >> 2;
        const int cc   = lane & 3;
        const int m0   = mt * 16 + g, m1 = m0 + 8;
        const int h0   = hbase + ks * 8 + cc, h1 = h0 + 4;
        const float wh0 = __ldg(jw1f + h0), wh1 = __ldg(jw1f + h1);
        const float bh0 = __ldg(jb1f + h0), bh1 = __ldg(jb1f + h1);
        const float x0 = xs[fi * 128 + m0], g0 = wts[fi * 128 + m0];
        const float x1 = xs[fi * 128 + m1], g1 = wts[fi * 128 + m1];
        const float v00 = eluf(fmaf(x0, wh0, bh0)) * g0;   // a0 (m0,h0)
        const float v10 = eluf(fmaf(x1, wh0, bh0)) * g1;   // a1 (m1,h0)
        const float v01 = eluf(fmaf(x0, wh1, bh1)) * g0;   // a2 (m0,h1)
        const float v11 = eluf(fmaf(x1, wh1, bh1)) * g1;   // a3 (m1,h1)
        dst[s] = make_uint4(tf32_rna(v00), tf32_rna(v10), tf32_rna(v01), tf32_rna(v11));
    }
}

__global__ __launch_bounds__(512, 1)
void main_kernel(const float* __restrict__ x,
                 const float* __restrict__ jw1, const float* __restrict__ jb1)
{
    extern __shared__ float sm[];
    float* xs  = sm + XSOFF;    // [fi(32)][m(128)]
    float* wts = sm + WTSOFF;

    const int tid   = threadIdx.x;
    const int w     = tid >> 5;
    const int lane  = tid & 31;
    const int half  = blockIdx.x & 1;
    const int tile  = blockIdx.x >> 1;
    const int r0    = tile * 128;
    const int fbase = half * 32;

    const int mt0 = (w >> 2) * 2, mt1 = mt0 + 1;   // warp's m16-tiles
    const int nt0 = (w & 3) * 4;                    // warp's first n8-tile

    const unsigned smb = smem_u32(sm);

    // stage xs / wts
    for (int i = tid; i < 32 * 128; i += 512) {
        const int fi = i >> 7, m = i & 127;
        xs[i]  = x[(r0 + m) * FF + fbase + fi];
        wts[i] = g_wt[(r0 + m) * FF + fbase + fi];
    }

    // prologue cp.async: B2 (group0), B chunk 0 (group1), B chunk 1 (group2)
    {
        const unsigned* src = g_b2f[half];
#pragma unroll
        for (int k = 0; k < 2; k++) {
            const int idx = tid + k * 512;
            cpasync16(smb + (B2OFF + idx * 4) * 4, src + idx * 4);
        }
        CP_COMMIT();
    }
#pragma unroll
    for (int c = 0; c < 2; c++) {
        const unsigned* src = g_bf[fbase] + c * 8192;   // f = fbase, chunks 0,1
#pragma unroll
        for (int k = 0; k < 4; k++) {
            const int idx = tid + k * 512;
            cpasync16(smb + (BROFF + c * 8192 + idx * 4) * 4, src + idx * 4);
        }
        CP_COMMIT();
    }

    __syncthreads();   // xs/wts visible

    // gen A2 (w_t fragment tile, K=32) and A chunk 0
    {
        uint4* dst = (uint4*)(sm + A2OFF);
#pragma unroll
        for (int j = 0; j < 2; j++) {
            const int s    = tid + j * 512;    // 0..1023
            const int ln   = s & 31;
            const int mt   = (s >> 5) & 7;
            const int ks   = s >> 8;           // 0..3
            const int g    = ln >> 2;
            const int cc   = ln & 3;
            const int m0   = mt * 16 + g, m1 = m0 + 8;
            const int k0   = ks * 8 + cc, k1 = k0 + 4;
            dst[s] = make_uint4(tf32_rna(wts[k0 * 128 + m0]),
                                tf32_rna(wts[k0 * 128 + m1]),
                                tf32_rna(wts[k1 * 128 + m0]),
                                tf32_rna(wts[k1 * 128 + m1]));
        }
    }
    gen_chunk(sm, A0OFF, xs, wts, jw1 + fbase * HH, jb1 + fbase * HH, 0, 0, tid);

    CP_WAIT(2);        // B2 arrived
    __syncthreads();   // A2 + A0 + B2 visible

    float acc[2][4][4];
#pragma unroll
    for (int i = 0; i < 2; i++)
#pragma unroll
        for (int jn = 0; jn < 4; jn++)
#pragma unroll
            for (int k = 0; k < 4; k++) acc[i][jn][k] = 0.f;

    // ---- bias GEMM: 4 K-steps of w_t @ jb3^T ----
    {
        const uint4* Af = (const uint4*)(sm + A2OFF);
        const uint2* Bf = (const uint2*)(sm + B2OFF);
#pragma unroll
        for (int ks = 0; ks < 4; ks++) {
            const uint4 a0 = Af[(ks * 8 + mt0) * 32 + lane];
            const uint4 a1 = Af[(ks * 8 + mt1) * 32 + lane];
#pragma unroll
            for (int jn = 0; jn < 4; jn++) {
                const uint2 b = Bf[(ks * 16 + nt0 + jn) * 32 + lane];
                mma8(acc[0][jn], a0, b);
                mma8(acc[1][jn], a1, b);
            }
        }
    }

    // ---- main loop: 64 chunks of 64h ----
    for (int c = 0; c < 64; c++) {
        // wait for B(c): pending groups are B(c), B(c+1)
        if (c < 63) { CP_WAIT(1); } else { CP_WAIT(0); }
        __syncthreads();   // A(c) gen'd by all; B(c) visible; old buffers free

        // issue B(c+2) into ring slot (c+2)%3 (slot of retired B(c-1))
        if (c < 62) {
            const int cn = c + 2;
            const unsigned* src = g_bf[fbase + (cn >> 1)] + (cn & 1) * 8192;
            const int slot = cn % 3;
#pragma unroll
            for (int k = 0; k < 4; k++) {
                const int idx = tid + k * 512;
                cpasync16(smb + (BROFF + slot * 8192 + idx * 4) * 4, src + idx * 4);
            }
            CP_COMMIT();
        }

        // MMA: 8 K-steps from A[c&1], Bring[c%3]
        {
            const uint4* Af = (const uint4*)(sm + ((c & 1) ? A1OFF : A0OFF));
            const uint2* Bf = (const uint2*)(sm + BROFF + (c % 3) * 8192);
#pragma unroll
            for (int ks = 0; ks < 8; ks++) {
                const uint4 a0 = Af[(ks * 8 + mt0) * 32 + lane];
                const uint4 a1 = Af[(ks * 8 + mt1) * 32 + lane];
#pragma unroll
                for (int jn = 0; jn < 4; jn++) {
                    const uint2 b = Bf[(ks * 16 + nt0 + jn) * 32 + lane];
                    mma8(acc[0][jn], a0, b);
                    mma8(acc[1][jn], a1, b);
                }
            }
        }

        // gen A(c+1) into the other A buffer
        if (c < 63) {
            const int cn = c + 1;
            const int fi = cn >> 1;
            gen_chunk(sm, (cn & 1) ? A1OFF : A0OFF, xs, wts,
                      jw1 + (fbase + fi) * HH, jb1 + (fbase + fi) * HH,
                      fi, (cn & 1) * 64, tid);
        }
    }

    // ---- epilogue: write split-K partial ----
    {
        const int g  = lane >> 2;
        const int cc = lane & 3;
        float* pout = g_part[half];
#pragma unroll
        for (int mi = 0; mi < 2; mi++) {
            const int mrow = r0 + (mt0 + mi) * 16 + g;
#pragma unroll
            for (int jn = 0; jn < 4; jn++) {
                const int ncol = (nt0 + jn) * 8 + cc * 2;
                *(float2*)&pout[mrow * HH + ncol] =
                    make_float2(acc[mi][jn][0], acc[mi][jn][1]);
                *(float2*)&pout[(mrow + 8) * HH + ncol] =
                    make_float2(acc[mi][jn][2], acc[mi][jn][3]);
            }
        }
    }
}

// ---------------------------------------------------------------------------
// Combine kernel: out = part0 + part1
// ---------------------------------------------------------------------------
__global__ __launch_bounds__(256, 1)
void combine_kernel(float* __restrict__ out)
{
    const int i = blockIdx.x * 256 + threadIdx.x;
    const float4 a = ((const float4*)g_part[0])[i];
    const float4 b = ((const float4*)g_part[1])[i];
    float4 r;
    r.x = a.x + b.x; r.y = a.y + b.y; r.z = a.z + b.z; r.w = a.w + b.w;
    ((float4*)out)[i] = r;
}

// ---------------------------------------------------------------------------
extern "C" void kernel_launch(void* const* d_in, const int* in_sizes, int n_in,
                              void* d_out, int out_size)
{
    (void)in_sizes; (void)n_in; (void)out_size;
    const float* x   = (const float*)d_in[0];
    const float* s   = (const float*)d_in[1];
    const float* w1  = (const float*)d_in[2];
    const float* b1  = (const float*)d_in[3];
    const float* w2  = (const float*)d_in[4];
    const float* b2  = (const float*)d_in[5];
    const float* w3  = (const float*)d_in[6];
    const float* b3  = (const float*)d_in[7];
    const float* jw1 = (const float*)d_in[8];
    const float* jb1 = (const float*)d_in[9];
    const float* jw3 = (const float*)d_in[10];
    const float* jb3 = (const float*)d_in[11];
    float* out = (float*)d_out;

    (void)cudaFuncSetAttribute(logits_kernel,  cudaFuncAttributeMaxDynamicSharedMemorySize, LOG_SMEM_BYTES);
    (void)cudaFuncSetAttribute(softmax_kernel, cudaFuncAttributeMaxDynamicSharedMemorySize, SMX_SMEM_BYTES);
    (void)cudaFuncSetAttribute(main_kernel,    cudaFuncAttributeMaxDynamicSharedMemorySize, MAIN_SMEM_BYTES);

    prep_kernel   <<<66, 256>>>(jw3, jb3);
    logits_kernel <<<128, 256, LOG_SMEM_BYTES>>>(x, s, w1, b1, w2, b2, w3, b3);
    softmax_kernel<<<64, 512, SMX_SMEM_BYTES>>>();
    main_kernel   <<<128, 512, MAIN_SMEM_BYTES>>>(x, jw1, jb1);
    combine_kernel<<<(MROWS * HH) / (4 * 256), 256>>>(out);
}